// round 5
// baseline (speedup 1.0000x reference)
#include <cuda_runtime.h>
#include <math.h>

// ---------------------------------------------------------------------------
// LSTM layer: B=32, T=512, D=1024, H=1024
// ---------------------------------------------------------------------------

#define BB 32
#define TT 512
#define DD 1024
#define HH 1024

typedef unsigned long long u64;

__device__ __forceinline__ u64 pack2(float x, float y) {
    u64 r; asm("mov.b64 %0, {%1, %2};" : "=l"(r) : "f"(x), "f"(y)); return r;
}
__device__ __forceinline__ void ffma2(u64 &d, u64 a, u64 b) {
    asm("fma.rn.f32x2 %0, %1, %2, %0;" : "+l"(d) : "l"(a), "l"(b));
}
__device__ __forceinline__ float2 unpack2(u64 v) {
    float2 f; asm("mov.b64 {%0, %1}, %2;" : "=f"(f.x), "=f"(f.y) : "l"(v)); return f;
}
__device__ __forceinline__ void cp_async16(void* smem_dst, const void* gsrc) {
    unsigned s = (unsigned)__cvta_generic_to_shared(smem_dst);
    asm volatile("cp.async.cg.shared.global [%0], [%1], 16;" :: "r"(s), "l"(gsrc));
}
#define CP_COMMIT() asm volatile("cp.async.commit_group;")
#define CP_WAIT(n)  asm volatile("cp.async.wait_group %0;" :: "n"(n))

// Scratch (device globals: allocation-free rule)
__device__ float g_xp[(size_t)TT * BB * 4 * HH];      // 256 MB  [m][gate*1024+j]
__device__ float g_states[(size_t)TT * BB * HH];      // 64 MB   [m][j]
__device__ float g_hT[(size_t)HH * BB];               // 128 KB  [k(=j)][b]
__device__ unsigned g_bar_count = 0;
__device__ unsigned g_bar_gen = 0;

// ===========================================================================
// Kernel 1: input projection GEMM. M=16384 (m=t*32+b), N=4096, K=1024.
// (unchanged from R3)
// ===========================================================================
__global__ void __launch_bounds__(256) k_input_gemm(
    const float* __restrict__ x,
    const float* __restrict__ Wi, const float* __restrict__ Wf,
    const float* __restrict__ Wg, const float* __restrict__ Wc,
    const float* __restrict__ bi, const float* __restrict__ bf,
    const float* __restrict__ bg, const float* __restrict__ bc)
{
    __shared__ float As[2][8][264];   // duplicated, padded
    __shared__ float Bs[2][8][128];

    const int tid = threadIdx.x;
    const int tx = tid & 15;
    const int ty = tid >> 4;
    const int nblk = blockIdx.x * 128;
    const int mblk = blockIdx.y * 128;

    const int gate = nblk >> 10;
    const float* W    = (gate == 0) ? Wi : (gate == 1) ? Wf : (gate == 2) ? Wg : Wc;
    const float* bias = (gate == 0) ? bi : (gate == 1) ? bf : (gate == 2) ? bg : bc;
    const int jb = nblk & 1023;

    const int row_a = tid >> 1;
    const int ka = (tid & 1) * 4;
    const int m_a = mblk + row_a;                 // m = t*32 + b
    const float* arow = x + ((size_t)((m_a & 31) * TT + (m_a >> 5))) * DD;

    const int kb = tid >> 5;
    const int nb = (tid & 31) * 4;

    {
        float4 av = *(const float4*)&arow[ka];
        float4 bv = *(const float4*)&W[(size_t)kb * HH + jb + nb];
        *(float2*)&As[0][ka + 0][2 * row_a] = make_float2(av.x, av.x);
        *(float2*)&As[0][ka + 1][2 * row_a] = make_float2(av.y, av.y);
        *(float2*)&As[0][ka + 2][2 * row_a] = make_float2(av.z, av.z);
        *(float2*)&As[0][ka + 3][2 * row_a] = make_float2(av.w, av.w);
        *(float4*)&Bs[0][kb][nb] = bv;
    }
    __syncthreads();

    u64 acc2[8][4];
#pragma unroll
    for (int r = 0; r < 8; ++r)
#pragma unroll
        for (int c = 0; c < 4; ++c) acc2[r][c] = 0ull;

#pragma unroll 1
    for (int k0 = 0; k0 < DD; k0 += 8) {
        const int cur = (k0 >> 3) & 1;
        float4 a_n, b_n;
        const bool more = (k0 + 8) < DD;
        if (more) {
            a_n = *(const float4*)&arow[k0 + 8 + ka];
            b_n = *(const float4*)&W[(size_t)(k0 + 8 + kb) * HH + jb + nb];
        }
#pragma unroll
        for (int kk = 0; kk < 8; ++kk) {
            ulonglong2 al0 = *(const ulonglong2*)&As[cur][kk][8 * ty];
            ulonglong2 al1 = *(const ulonglong2*)&As[cur][kk][8 * ty + 4];
            ulonglong2 au0 = *(const ulonglong2*)&As[cur][kk][128 + 8 * ty];
            ulonglong2 au1 = *(const ulonglong2*)&As[cur][kk][128 + 8 * ty + 4];
            ulonglong2 bl = *(const ulonglong2*)&Bs[cur][kk][tx * 4];
            ulonglong2 bu = *(const ulonglong2*)&Bs[cur][kk][64 + tx * 4];
            u64 ab[8] = {al0.x, al0.y, al1.x, al1.y, au0.x, au0.y, au1.x, au1.y};
            u64 bb[4] = {bl.x, bl.y, bu.x, bu.y};
#pragma unroll
            for (int r = 0; r < 8; ++r)
#pragma unroll
                for (int c = 0; c < 4; ++c)
                    ffma2(acc2[r][c], ab[r], bb[c]);
        }
        if (more) {
            const int nxt = cur ^ 1;
            *(float2*)&As[nxt][ka + 0][2 * row_a] = make_float2(a_n.x, a_n.x);
            *(float2*)&As[nxt][ka + 1][2 * row_a] = make_float2(a_n.y, a_n.y);
            *(float2*)&As[nxt][ka + 2][2 * row_a] = make_float2(a_n.z, a_n.z);
            *(float2*)&As[nxt][ka + 3][2 * row_a] = make_float2(a_n.w, a_n.w);
            *(float4*)&Bs[nxt][kb][nb] = b_n;
            __syncthreads();
        }
    }

#pragma unroll
    for (int ch = 0; ch < 2; ++ch) {
        const int cbase = ch * 64 + tx * 4;
        float4 bsv = *(const float4*)&bias[jb + cbase];
#pragma unroll
        for (int rh = 0; rh < 2; ++rh)
#pragma unroll
            for (int rr = 0; rr < 4; ++rr) {
                const int m = mblk + rh * 64 + ty * 4 + rr;
                float2 p0 = unpack2(acc2[rh * 4 + rr][ch * 2 + 0]);
                float2 p1 = unpack2(acc2[rh * 4 + rr][ch * 2 + 1]);
                float4 o;
                o.x = p0.x + bsv.x;
                o.y = p0.y + bsv.y;
                o.z = p1.x + bsv.z;
                o.w = p1.y + bsv.w;
                *(float4*)&g_xp[(size_t)m * 4096 + nblk + cbase] = o;
            }
    }
}

// ===========================================================================
// Kernel 2: persistent recurrent kernel, restructured.
// 128 blocks x 256 threads, 1 block/SM (200KB smem), grid sync per step.
// Block: 32 b x 8 j x 4 gates.  Thread (bg=tid&3, jg=(tid>>2)&3, ks=tid>>4):
//   tile 8b x 2j x 4g, k-slice = { q*256 + ks*16 + kk : q<4, kk<16 }.
// U resident in smem [k][jslot][g][jpair] with XOR swizzle (128KB).
// h staged per step via cp.async in 4 quarters, double-buffered, XOR-swizzled
// 16B chunks, row stride 36 floats. Reduction over 16 k-partials in overlay.
// ===========================================================================
#define NBLK2 128
#define SH_U_FLOATS 32768                     /* [1024][32] */
#define STAGE_ROW 36                          /* floats per k row (16B mult) */
#define STAGE_BUF_FLOATS (256 * STAGE_ROW)    /* 9216 per quarter buffer */
#define STAGE_FLOATS (2 * STAGE_BUF_FLOATS)   /* 18432 (red overlays: 17408) */
#define RED_BSTRIDE 34
#define SMEM2_FLOATS (SH_U_FLOATS + STAGE_FLOATS)
#define SMEM2_BYTES (SMEM2_FLOATS * 4)        /* 204800 B */

__device__ __forceinline__ void grid_sync()
{
    __syncthreads();
    if (threadIdx.x == 0) {
        __threadfence();
        unsigned gen = *(volatile unsigned*)&g_bar_gen;
        unsigned t = atomicAdd(&g_bar_count, 1);
        if (t == NBLK2 - 1) {
            g_bar_count = 0;
            __threadfence();
            atomicExch(&g_bar_gen, gen + 1);
        } else {
            while (*(volatile unsigned*)&g_bar_gen == gen) { }
            __threadfence();
        }
    }
    __syncthreads();
}

__global__ void __launch_bounds__(256, 1) k_recurrent(
    const float* __restrict__ Ui, const float* __restrict__ Uf,
    const float* __restrict__ Ug, const float* __restrict__ Uc)
{
    extern __shared__ float smem[];
    float* sh_u   = smem;                       // [1024][32] swizzled
    float* sh_stg = smem + SH_U_FLOATS;         // 2 x [256][36]; red overlay

    const int tid = threadIdx.x;
    const int bg = tid & 3;                     // b block: b = bg*8 + bi
    const int jg = (tid >> 2) & 3;              // j pair: j = jg*2 + {0,1}
    const int ks = tid >> 4;                    // k split 0..15
    const int jb8 = blockIdx.x * 8;

    // ---- stage U once: sh_u[k*32 + jslot*8 + g*2 + {0,1}] ----
    // jslot = jgi ^ (k&3) ^ ((k>>4)&3)
    {
        const float* Us[4] = {Ui, Uf, Ug, Uc};
#pragma unroll 1
        for (int g = 0; g < 4; ++g) {
            const float* Up = Us[g];
            for (int i = tid; i < 4096; i += 256) {
                const int k = i >> 2;
                const int jgi = i & 3;
                float2 v = *(const float2*)&Up[(size_t)k * HH + jb8 + jgi * 2];
                const int jslot = jgi ^ ((k ^ (k >> 4)) & 3);
                *(float2*)&sh_u[k * 32 + jslot * 8 + g * 2] = v;
            }
        }
    }

    // per-thread constants
    const int s_h = ks & 7;                            // h chunk swizzle
    const int hoff0 = (((bg * 2) ^ s_h) * 4);          // float offsets in row
    const int hoff1 = (((bg * 2 + 1) ^ s_h) * 4);
    const int jslot_base = jg ^ (ks & 3);              // ^ (kk&3) per kk

    // reduction/output identity: (rb, rj) owns (b=rb, j=jb8+rj)
    const int rb = tid >> 3;
    const int rj = tid & 7;
    float c = 0.0f;

    __syncthreads();

    for (int t = 0; t < TT; ++t) {
        float z[4];

        if (t == 0) {
            z[0] = 0.f; z[1] = 0.f; z[2] = 0.f; z[3] = 0.f;
        } else {
            u64 acc2[4][8];                 // [gate][bi], packed j-pair
#pragma unroll
            for (int g = 0; g < 4; ++g)
#pragma unroll
                for (int bi = 0; bi < 8; ++bi) acc2[g][bi] = 0ull;

            // prologue: prefetch quarter 0 into buf0
            {
                const float* src = g_hT;                  // quarter 0
                float* dst = sh_stg;
#pragma unroll
                for (int i = 0; i < 8; ++i) {
                    const int cch = tid + i * 256;        // 0..2047
                    const int kl = cch >> 3;
                    const int slot = (cch & 7) ^ ((cch >> 7) & 7);
                    cp_async16(dst + kl * STAGE_ROW + slot * 4, src + cch * 4);
                }
                CP_COMMIT();
            }

#pragma unroll 1
            for (int q = 0; q < 4; ++q) {
                if (q < 3) {
                    // prefetch quarter q+1 into other buffer
                    const float* src = g_hT + (size_t)(q + 1) * 256 * 32;
                    float* dst = sh_stg + ((q + 1) & 1) * STAGE_BUF_FLOATS;
#pragma unroll
                    for (int i = 0; i < 8; ++i) {
                        const int cch = tid + i * 256;
                        const int kl = cch >> 3;
                        const int slot = (cch & 7) ^ ((cch >> 7) & 7);
                        cp_async16(dst + kl * STAGE_ROW + slot * 4, src + cch * 4);
                    }
                    CP_COMMIT();
                    CP_WAIT(1);              // quarter q's group done
                } else {
                    CP_WAIT(0);
                }
                __syncthreads();

                const float* hrow = sh_stg + (q & 1) * STAGE_BUF_FLOATS
                                  + (ks * 16) * STAGE_ROW;
                const float* ubase = sh_u + ((q * 256 + ks * 16) * 32);

#pragma unroll
                for (int kk = 0; kk < 16; ++kk) {
                    const float* hr = hrow + kk * STAGE_ROW;
                    float4 h0 = *(const float4*)(hr + hoff0);
                    float4 h1 = *(const float4*)(hr + hoff1);
                    const int jslot = jslot_base ^ (kk & 3);
                    const float* ur = ubase + kk * 32 + jslot * 8;
                    ulonglong2 u01 = *(const ulonglong2*)ur;        // g0, g1
                    ulonglong2 u23 = *(const ulonglong2*)(ur + 4);  // g2, g3
                    u64 hb[8];
                    hb[0] = pack2(h0.x, h0.x); hb[1] = pack2(h0.y, h0.y);
                    hb[2] = pack2(h0.z, h0.z); hb[3] = pack2(h0.w, h0.w);
                    hb[4] = pack2(h1.x, h1.x); hb[5] = pack2(h1.y, h1.y);
                    hb[6] = pack2(h1.z, h1.z); hb[7] = pack2(h1.w, h1.w);
                    u64 uu[4] = {u01.x, u01.y, u23.x, u23.y};
#pragma unroll
                    for (int g = 0; g < 4; ++g)
#pragma unroll
                        for (int bi = 0; bi < 8; ++bi)
                            ffma2(acc2[g][bi], hb[bi], uu[g]);
                }
                __syncthreads();
            }

            // ---- write partials to overlay: red[(ks*32+b)*34 + g*8 + jg*2] ----
            float* red = sh_stg;
#pragma unroll
            for (int g = 0; g < 4; ++g)
#pragma unroll
                for (int bi = 0; bi < 8; ++bi) {
                    const int b = bg * 8 + bi;
                    *(u64*)&red[(ks * 32 + b) * RED_BSTRIDE + g * 8 + jg * 2] =
                        acc2[g][bi];
                }
            __syncthreads();

            // ---- reduce 16 partials per (b, gate, j) ----
#pragma unroll
            for (int g = 0; g < 4; ++g) {
                float s = 0.0f;
#pragma unroll
                for (int qq = 0; qq < 16; ++qq)
                    s += red[(qq * 32 + rb) * RED_BSTRIDE + g * 8 + rj];
                z[g] = s;
            }
        }

        // ---- gates + state update ----
        const float* xp = g_xp + ((size_t)t * 32 + rb) * 4096 + jb8 + rj;
        float zi = z[0] + xp[0];
        float zf = z[1] + xp[1024];
        float zg = z[2] + xp[2048];
        float zc = z[3] + xp[3072];

        float ig = 1.0f / (1.0f + __expf(-zi));
        float fg = 1.0f / (1.0f + __expf(-zf));
        float gg = 1.0f / (1.0f + __expf(-zg));
        float ct = tanhf(zc);
        c = fg * c + ig * ct;
        float h = gg * tanhf(c);

        g_states[((size_t)t * 32 + rb) * HH + jb8 + rj] = h;
        g_hT[(size_t)(jb8 + rj) * 32 + rb] = h;

        grid_sync();
    }
}

// ===========================================================================
// Kernel 3: output projection + ReLU. M=16384, N=1024, K=1024. (unchanged)
// ===========================================================================
__global__ void __launch_bounds__(256) k_output_gemm(
    const float* __restrict__ Wo, const float* __restrict__ bo,
    float* __restrict__ out)
{
    __shared__ float As[2][8][264];
    __shared__ float Bs[2][8][128];

    const int tid = threadIdx.x;
    const int tx = tid & 15;
    const int ty = tid >> 4;
    const int nblk = blockIdx.x * 128;
    const int mblk = blockIdx.y * 128;

    const int row_a = tid >> 1;
    const int ka = (tid & 1) * 4;
    const float* arow = g_states + (size_t)(mblk + row_a) * HH;

    const int kb = tid >> 5;
    const int nb = (tid & 31) * 4;

    {
        float4 av = *(const float4*)&arow[ka];
        float4 bv = *(const float4*)&Wo[(size_t)kb * HH + nblk + nb];
        *(float2*)&As[0][ka + 0][2 * row_a] = make_float2(av.x, av.x);
        *(float2*)&As[0][ka + 1][2 * row_a] = make_float2(av.y, av.y);
        *(float2*)&As[0][ka + 2][2 * row_a] = make_float2(av.z, av.z);
        *(float2*)&As[0][ka + 3][2 * row_a] = make_float2(av.w, av.w);
        *(float4*)&Bs[0][kb][nb] = bv;
    }
    __syncthreads();

    u64 acc2[8][4];
#pragma unroll
    for (int r = 0; r < 8; ++r)
#pragma unroll
        for (int c = 0; c < 4; ++c) acc2[r][c] = 0ull;

#pragma unroll 1
    for (int k0 = 0; k0 < HH; k0 += 8) {
        const int cur = (k0 >> 3) & 1;
        float4 a_n, b_n;
        const bool more = (k0 + 8) < HH;
        if (more) {
            a_n = *(const float4*)&arow[k0 + 8 + ka];
            b_n = *(const float4*)&Wo[(size_t)(k0 + 8 + kb) * HH + nblk + nb];
        }
#pragma unroll
        for (int kk = 0; kk < 8; ++kk) {
            ulonglong2 al0 = *(const ulonglong2*)&As[cur][kk][8 * ty];
            ulonglong2 al1 = *(const ulonglong2*)&As[cur][kk][8 * ty + 4];
            ulonglong2 au0 = *(const ulonglong2*)&As[cur][kk][128 + 8 * ty];
            ulonglong2 au1 = *(const ulonglong2*)&As[cur][kk][128 + 8 * ty + 4];
            ulonglong2 bl = *(const ulonglong2*)&Bs[cur][kk][tx * 4];
            ulonglong2 bu = *(const ulonglong2*)&Bs[cur][kk][64 + tx * 4];
            u64 ab[8] = {al0.x, al0.y, al1.x, al1.y, au0.x, au0.y, au1.x, au1.y};
            u64 bb[4] = {bl.x, bl.y, bu.x, bu.y};
#pragma unroll
            for (int r = 0; r < 8; ++r)
#pragma unroll
                for (int c = 0; c < 4; ++c)
                    ffma2(acc2[r][c], ab[r], bb[c]);
        }
        if (more) {
            const int nxt = cur ^ 1;
            *(float2*)&As[nxt][ka + 0][2 * row_a] = make_float2(a_n.x, a_n.x);
            *(float2*)&As[nxt][ka + 1][2 * row_a] = make_float2(a_n.y, a_n.y);
            *(float2*)&As[nxt][ka + 2][2 * row_a] = make_float2(a_n.z, a_n.z);
            *(float2*)&As[nxt][ka + 3][2 * row_a] = make_float2(a_n.w, a_n.w);
            *(float4*)&Bs[nxt][kb][nb] = b_n;
            __syncthreads();
        }
    }

#pragma unroll
    for (int ch = 0; ch < 2; ++ch) {
        const int cbase = ch * 64 + tx * 4;
        float4 bsv = *(const float4*)&bo[nblk + cbase];
#pragma unroll
        for (int rh = 0; rh < 2; ++rh)
#pragma unroll
            for (int rr = 0; rr < 4; ++rr) {
                const int m = mblk + rh * 64 + ty * 4 + rr;   // m = t*32 + b
                const int b = m & 31;
                const int tt = m >> 5;
                float2 p0 = unpack2(acc2[rh * 4 + rr][ch * 2 + 0]);
                float2 p1 = unpack2(acc2[rh * 4 + rr][ch * 2 + 1]);
                float4 o;
                o.x = fmaxf(p0.x + bsv.x, 0.0f);
                o.y = fmaxf(p0.y + bsv.y, 0.0f);
                o.z = fmaxf(p1.x + bsv.z, 0.0f);
                o.w = fmaxf(p1.y + bsv.w, 0.0f);
                *(float4*)&out[((size_t)b * TT + tt) * HH + nblk + cbase] = o;
            }
    }
}

// ---------------------------------------------------------------------------
// Launch
// ---------------------------------------------------------------------------
extern "C" void kernel_launch(void* const* d_in, const int* in_sizes, int n_in,
                              void* d_out, int out_size)
{
    const float* x  = (const float*)d_in[0];
    const float* Wi = (const float*)d_in[1];
    const float* Ui = (const float*)d_in[2];
    const float* Wf = (const float*)d_in[3];
    const float* Uf = (const float*)d_in[4];
    const float* Wg = (const float*)d_in[5];
    const float* Ug = (const float*)d_in[6];
    const float* Wc = (const float*)d_in[7];
    const float* Uc = (const float*)d_in[8];
    const float* Wo = (const float*)d_in[9];
    const float* bi = (const float*)d_in[10];
    const float* bf = (const float*)d_in[11];
    const float* bg = (const float*)d_in[12];
    const float* bc = (const float*)d_in[13];
    const float* bo = (const float*)d_in[14];
    float* out = (float*)d_out;

    static bool attr_set = false;
    if (!attr_set) {
        cudaFuncSetAttribute(k_recurrent,
                             cudaFuncAttributeMaxDynamicSharedMemorySize,
                             SMEM2_BYTES);
        attr_set = true;
    }

    // 1) input projection: grid (4096/128, 16384/128)
    k_input_gemm<<<dim3(32, 128), 256>>>(x, Wi, Wf, Wg, Wc, bi, bf, bg, bc);

    // 2) recurrence: persistent kernel, 128 blocks, 200KB smem
    k_recurrent<<<NBLK2, 256, SMEM2_BYTES>>>(Ui, Uf, Ug, Uc);

    // 3) output projection: grid (1024/128, 16384/128)
    k_output_gemm<<<dim3(8, 128), 256>>>(Wo, bo, out);
}

// round 7
// speedup vs baseline: 1.2567x; 1.2567x over previous
#include <cuda_runtime.h>
#include <cuda_bf16.h>
#include <math.h>
#include <stdint.h>

// ---------------------------------------------------------------------------
// LSTM layer: B=32, T=512, D=1024, H=1024
// k1/k3: bf16x3 split GEMM on tensor cores via mma.sync (base-target PTX).
// k2: persistent fp32 recurrent kernel (best measured version, unchanged).
// ---------------------------------------------------------------------------

#define BB 32
#define TT 512
#define DD 1024
#define HH 1024

typedef unsigned long long u64;

// ---------------- PTX helpers (all base-target) ----------------
__device__ __forceinline__ u64 pack2(float x, float y) {
    u64 r; asm("mov.b64 %0, {%1, %2};" : "=l"(r) : "f"(x), "f"(y)); return r;
}
__device__ __forceinline__ void ffma2(u64 &d, u64 a, u64 b) {
    asm("fma.rn.f32x2 %0, %1, %2, %0;" : "+l"(d) : "l"(a), "l"(b));
}
__device__ __forceinline__ void cp_async16(void* smem_dst, const void* gsrc) {
    unsigned s = (unsigned)__cvta_generic_to_shared(smem_dst);
    asm volatile("cp.async.cg.shared.global [%0], [%1], 16;" :: "r"(s), "l"(gsrc));
}
#define CP_COMMIT() asm volatile("cp.async.commit_group;")
#define CP_WAIT(n)  asm volatile("cp.async.wait_group %0;" :: "n"(n))

__device__ __forceinline__ uint32_t smem_u32(const void* p) {
    return (uint32_t)__cvta_generic_to_shared(p);
}
__device__ __forceinline__ void ldm_x4(uint32_t* r, uint32_t addr) {
    asm volatile("ldmatrix.sync.aligned.m8n8.x4.shared.b16 {%0,%1,%2,%3}, [%4];"
        : "=r"(r[0]), "=r"(r[1]), "=r"(r[2]), "=r"(r[3]) : "r"(addr));
}
__device__ __forceinline__ void mma_bf16(float* d, const uint32_t* a,
                                         uint32_t b0, uint32_t b1) {
    asm volatile(
        "mma.sync.aligned.m16n8k16.row.col.f32.bf16.bf16.f32 "
        "{%0,%1,%2,%3}, {%4,%5,%6,%7}, {%8,%9}, {%0,%1,%2,%3};"
        : "+f"(d[0]), "+f"(d[1]), "+f"(d[2]), "+f"(d[3])
        : "r"(a[0]), "r"(a[1]), "r"(a[2]), "r"(a[3]), "r"(b0), "r"(b1));
}

// ---------------- scratch globals ----------------
__device__ float g_xp[(size_t)TT * BB * 4 * HH];      // 256 MB
__device__ float g_states[(size_t)TT * BB * HH];      // 64 MB
__device__ float g_hT[(size_t)HH * BB];               // 128 KB
__device__ unsigned g_bar_count = 0;
__device__ unsigned g_bar_gen = 0;

__device__ __nv_bfloat16 g_A0[(size_t)16384 * 1024];  // A hi (x, later states)
__device__ __nv_bfloat16 g_A1[(size_t)16384 * 1024];  // A lo
__device__ __nv_bfloat16 g_B0[(size_t)4096 * 1024];   // W^T hi  [n][k]
__device__ __nv_bfloat16 g_B1[(size_t)4096 * 1024];   // W^T lo
__device__ __nv_bfloat16 g_Wo0[(size_t)1024 * 1024];  // Wo^T hi
__device__ __nv_bfloat16 g_Wo1[(size_t)1024 * 1024];  // Wo^T lo
__device__ float g_bias4[4096];

// ===========================================================================
// Conversion kernels
// ===========================================================================
__global__ void k_conv_x(const float* __restrict__ x)   // grid 16384, block 256
{
    const int m = blockIdx.x;                 // m = t*32 + b
    const float* row = x + ((size_t)(m & 31) * TT + (m >> 5)) * DD;
    const int c = threadIdx.x * 4;
    float4 v = *(const float4*)&row[c];
    __nv_bfloat16 h0 = __float2bfloat16(v.x), h1 = __float2bfloat16(v.y);
    __nv_bfloat16 h2 = __float2bfloat16(v.z), h3 = __float2bfloat16(v.w);
    __nv_bfloat16 l0 = __float2bfloat16(v.x - __bfloat162float(h0));
    __nv_bfloat16 l1 = __float2bfloat16(v.y - __bfloat162float(h1));
    __nv_bfloat16 l2 = __float2bfloat16(v.z - __bfloat162float(h2));
    __nv_bfloat16 l3 = __float2bfloat16(v.w - __bfloat162float(h3));
    size_t o = (size_t)m * 1024 + c;
    *(ushort4*)&g_A0[o] = make_ushort4(*(unsigned short*)&h0, *(unsigned short*)&h1,
                                       *(unsigned short*)&h2, *(unsigned short*)&h3);
    *(ushort4*)&g_A1[o] = make_ushort4(*(unsigned short*)&l0, *(unsigned short*)&l1,
                                       *(unsigned short*)&l2, *(unsigned short*)&l3);
}

__global__ void k_conv_states()                         // grid 16384, block 256
{
    const int m = blockIdx.x;
    const float* row = g_states + (size_t)m * 1024;
    const int c = threadIdx.x * 4;
    float4 v = *(const float4*)&row[c];
    __nv_bfloat16 h0 = __float2bfloat16(v.x), h1 = __float2bfloat16(v.y);
    __nv_bfloat16 h2 = __float2bfloat16(v.z), h3 = __float2bfloat16(v.w);
    __nv_bfloat16 l0 = __float2bfloat16(v.x - __bfloat162float(h0));
    __nv_bfloat16 l1 = __float2bfloat16(v.y - __bfloat162float(h1));
    __nv_bfloat16 l2 = __float2bfloat16(v.z - __bfloat162float(h2));
    __nv_bfloat16 l3 = __float2bfloat16(v.w - __bfloat162float(h3));
    size_t o = (size_t)m * 1024 + c;
    *(ushort4*)&g_A0[o] = make_ushort4(*(unsigned short*)&h0, *(unsigned short*)&h1,
                                       *(unsigned short*)&h2, *(unsigned short*)&h3);
    *(ushort4*)&g_A1[o] = make_ushort4(*(unsigned short*)&l0, *(unsigned short*)&l1,
                                       *(unsigned short*)&l2, *(unsigned short*)&l3);
}

// transpose + split: W[k][n] -> d[orow_base + n][k] (hi/lo)
__global__ void k_transpose_split(const float* __restrict__ W,
                                  __nv_bfloat16* __restrict__ d0,
                                  __nv_bfloat16* __restrict__ d1,
                                  int orow_base)       // grid (32, 32), block (32,8)
{
    __shared__ float tile[32][33];
    const int kt = blockIdx.x * 32, nt = blockIdx.y * 32;
    const int tx = threadIdx.x, ty = threadIdx.y;
#pragma unroll
    for (int i = 0; i < 4; ++i)
        tile[ty + 8 * i][tx] = W[(size_t)(kt + ty + 8 * i) * 1024 + nt + tx];
    __syncthreads();
#pragma unroll
    for (int i = 0; i < 4; ++i) {
        float v = tile[tx][ty + 8 * i];
        __nv_bfloat16 hi = __float2bfloat16(v);
        __nv_bfloat16 lo = __float2bfloat16(v - __bfloat162float(hi));
        size_t o = (size_t)(orow_base + nt + ty + 8 * i) * 1024 + kt + tx;
        d0[o] = hi; d1[o] = lo;
    }
}

__global__ void k_bias_concat(const float* bi, const float* bf_,
                              const float* bg, const float* bc)  // grid 16, block 256
{
    int idx = blockIdx.x * 256 + threadIdx.x;
    int g = idx >> 10, j = idx & 1023;
    const float* b = (g == 0) ? bi : (g == 1) ? bf_ : (g == 2) ? bg : bc;
    g_bias4[idx] = b[j];
}

// ===========================================================================
// bf16x3 GEMM via mma.sync: C[m][n] = sum_k (A0+A1)[m][k]*(B0+B1)[n][k]
// (3 products: A0B0 + A0B1 + A1B0, shared fp32 accumulators)
// CTA tile 128x128, 8 warps (4m x 2n), warp tile 32x64, k-chunk 32,
// cp.async double buffer. Smem tile row stride 80B (conflict-free ldmatrix).
// mode 0: out = g_xp[m][4096] + bias, no relu
// mode 1: out = outp[((m&31)*512 + (m>>5))*1024 + n] + bias, relu
// ===========================================================================
#define TROW 80                       /* bytes per smem tile row (32 bf16 + pad) */
#define TILE_BYTES (128 * TROW)       /* 10240 */
#define STAGE_BYTES (4 * TILE_BYTES)  /* 40960 */
#define GSMEM_BYTES (2 * STAGE_BYTES) /* 81920 */

__global__ void __launch_bounds__(256) k_gemm_tc(
    const __nv_bfloat16* __restrict__ A0, const __nv_bfloat16* __restrict__ A1,
    const __nv_bfloat16* __restrict__ B0, const __nv_bfloat16* __restrict__ B1,
    const float* __restrict__ bias, float* __restrict__ outp, int mode)
{
    extern __shared__ char smem[];
    __shared__ float sh_bias[128];

    const int tid = threadIdx.x;
    const int wid = tid >> 5;
    const int lane = tid & 31;
    const int nblk = blockIdx.x * 128;
    const int mblk = blockIdx.y * 128;

    const int wm = (wid >> 1) * 32;       // warp m offset in CTA tile
    const int wn = (wid & 1) * 64;        // warp n offset

    if (tid < 128) sh_bias[tid] = bias[nblk + tid];

    // global tile sources (row stride 2048 B)
    const char* srcs[4] = {
        (const char*)(A0 + (size_t)mblk * 1024),
        (const char*)(A1 + (size_t)mblk * 1024),
        (const char*)(B0 + (size_t)nblk * 1024),
        (const char*)(B1 + (size_t)nblk * 1024) };

#define LOAD_CHUNK(kc, s) do {                                                  \
        char* stg = smem + (s) * STAGE_BYTES;                                    \
        _Pragma("unroll")                                                        \
        for (int i = 0; i < 8; ++i) {                                            \
            const int ch = tid + i * 256;         /* 0..2047 */                  \
            const int tix = ch >> 9;                                             \
            const int q = ch & 511;                                              \
            const int r = q >> 2;                                                \
            const int cc = q & 3;                                                \
            cp_async16(stg + tix * TILE_BYTES + r * TROW + cc * 16,              \
                       srcs[tix] + (size_t)r * 2048 + (kc) * 64 + cc * 16);      \
        }                                                                        \
        CP_COMMIT();                                                             \
    } while (0)

    float acc[2][8][4];
#pragma unroll
    for (int mt = 0; mt < 2; ++mt)
#pragma unroll
        for (int nb = 0; nb < 8; ++nb)
#pragma unroll
            for (int r = 0; r < 4; ++r) acc[mt][nb][r] = 0.0f;

    LOAD_CHUNK(0, 0);

#pragma unroll 1
    for (int c = 0; c < 32; ++c) {
        const int cur = c & 1;
        if (c + 1 < 32) {
            LOAD_CHUNK(c + 1, cur ^ 1);
            CP_WAIT(1);
        } else {
            CP_WAIT(0);
        }
        __syncthreads();

        const uint32_t stg = smem_u32(smem) + cur * STAGE_BYTES;
        const uint32_t sA0 = stg;
        const uint32_t sA1 = stg + TILE_BYTES;
        const uint32_t sB0 = stg + 2 * TILE_BYTES;
        const uint32_t sB1 = stg + 3 * TILE_BYTES;

#pragma unroll
        for (int kt = 0; kt < 2; ++kt) {
            const uint32_t koff = kt * 32 + (lane >> 4) * 16;  // byte offset in row
            uint32_t a0f[2][4], a1f[2][4], b0f[4][4], b1f[4][4];
#pragma unroll
            for (int mt = 0; mt < 2; ++mt) {
                const uint32_t rb = (wm + mt * 16 + (lane & 15)) * TROW + koff;
                ldm_x4(a0f[mt], sA0 + rb);
                ldm_x4(a1f[mt], sA1 + rb);
            }
#pragma unroll
            for (int nt = 0; nt < 4; ++nt) {
                const uint32_t rb = (wn + nt * 16 + (lane & 15)) * TROW + koff;
                ldm_x4(b0f[nt], sB0 + rb);
                ldm_x4(b1f[nt], sB1 + rb);
            }
#pragma unroll
            for (int mt = 0; mt < 2; ++mt)
#pragma unroll
                for (int nb = 0; nb < 8; ++nb) {
                    const int nt = nb >> 1, h = nb & 1;
                    mma_bf16(acc[mt][nb], a0f[mt], b0f[nt][h], b0f[nt][h + 2]);
                    mma_bf16(acc[mt][nb], a0f[mt], b1f[nt][h], b1f[nt][h + 2]);
                    mma_bf16(acc[mt][nb], a1f[mt], b0f[nt][h], b0f[nt][h + 2]);
                }
        }
        __syncthreads();
    }

    // ---- epilogue ----
    const int mrow0 = mblk + wm + (lane >> 2);
    const int ncol0 = wn + 2 * (lane & 3);
#pragma unroll
    for (int mt = 0; mt < 2; ++mt)
#pragma unroll
        for (int nb = 0; nb < 8; ++nb) {
            const int n = ncol0 + nb * 8;
            const float bx = sh_bias[n], by = sh_bias[n + 1];
#pragma unroll
            for (int half = 0; half < 2; ++half) {
                const int m = mrow0 + mt * 16 + half * 8;
                float ox = acc[mt][nb][half * 2 + 0] + bx;
                float oy = acc[mt][nb][half * 2 + 1] + by;
                if (mode == 1) { ox = fmaxf(ox, 0.f); oy = fmaxf(oy, 0.f); }
                float* dst;
                if (mode == 0)
                    dst = g_xp + (size_t)m * 4096 + nblk + n;
                else
                    dst = outp + ((size_t)(m & 31) * TT + (m >> 5)) * 1024 + nblk + n;
                *(float2*)dst = make_float2(ox, oy);
            }
        }
}

// ===========================================================================
// Kernel 2: persistent recurrent kernel (best-measured version, unchanged)
// ===========================================================================
#define NBLK2 128
#define SH_U_FLOATS 32768           /* [1024][4][8] */
#define SH_H_FLOATS 16384           /* [512][32], aliased as red[8][32][34] */
#define SMEM2_BYTES ((SH_U_FLOATS + SH_H_FLOATS) * 4)

__device__ __forceinline__ void grid_sync()
{
    __syncthreads();
    if (threadIdx.x == 0) {
        __threadfence();
        unsigned gen = *(volatile unsigned*)&g_bar_gen;
        unsigned t = atomicAdd(&g_bar_count, 1);
        if (t == NBLK2 - 1) {
            g_bar_count = 0;
            __threadfence();
            atomicExch(&g_bar_gen, gen + 1);
        } else {
            while (*(volatile unsigned*)&g_bar_gen == gen) { }
            __threadfence();
        }
    }
    __syncthreads();
}

__global__ void __launch_bounds__(256, 1) k_recurrent(
    const float* __restrict__ Ui, const float* __restrict__ Uf,
    const float* __restrict__ Ug, const float* __restrict__ Uc)
{
    extern __shared__ float smemf[];
    float* sh_u = smemf;                 // [k:1024][g:4][jl:8]
    float* sh_h = smemf + SH_U_FLOATS;   // [k_half:512][b:32]

    const int tid = threadIdx.x;
    const int bg = tid & 7;
    const int jg = (tid >> 3) & 3;
    const int ks = tid >> 5;
    const int jb8 = blockIdx.x * 8;

    for (int i = tid; i < 8192; i += 256) {
        const int k = i >> 3;
        const int g = (i >> 1) & 3;
        const int j4 = (i & 1) * 4;
        const float* Up = (g == 0) ? Ui : (g == 1) ? Uf : (g == 2) ? Ug : Uc;
        float4 v = *(const float4*)&Up[(size_t)k * HH + jb8 + j4];
        *(float4*)&sh_u[(k * 4 + g) * 8 + j4] = v;
    }

    const int rb = tid >> 3;
    const int rj = tid & 7;
    float c = 0.0f;

    __syncthreads();

    for (int t = 0; t < TT; ++t) {
        u64 acc2[4][4];
#pragma unroll
        for (int g = 0; g < 4; ++g)
#pragma unroll
            for (int bi = 0; bi < 4; ++bi) acc2[g][bi] = 0ull;

#pragma unroll 1
        for (int p = 0; p < 2; ++p) {
            if (t == 0) {
                for (int i = tid * 4; i < SH_H_FLOATS; i += 1024)
                    *(float4*)&sh_h[i] = make_float4(0.f, 0.f, 0.f, 0.f);
            } else {
                const float* src = g_hT + (size_t)p * 512 * 32;
                for (int i = tid * 4; i < SH_H_FLOATS; i += 1024)
                    *(float4*)&sh_h[i] = *(const float4*)&src[i];
            }
            __syncthreads();

            const float* hp = sh_h + (ks * 64) * 32 + bg * 4;
            const float* up = sh_u + (p * 512 + ks * 64) * 32 + jg * 2;
#pragma unroll 8
            for (int kk = 0; kk < 64; ++kk) {
                float4 hv = *(const float4*)&hp[kk * 32];
                const float* u = &up[kk * 32];
                u64 u0 = *(const u64*)&u[0];
                u64 u1 = *(const u64*)&u[8];
                u64 u2 = *(const u64*)&u[16];
                u64 u3 = *(const u64*)&u[24];
                u64 hb[4];
                hb[0] = pack2(hv.x, hv.x);
                hb[1] = pack2(hv.y, hv.y);
                hb[2] = pack2(hv.z, hv.z);
                hb[3] = pack2(hv.w, hv.w);
                u64 uu[4] = {u0, u1, u2, u3};
#pragma unroll
                for (int g = 0; g < 4; ++g)
#pragma unroll
                    for (int bi = 0; bi < 4; ++bi)
                        ffma2(acc2[g][bi], hb[bi], uu[g]);
            }
            __syncthreads();
        }

        float* sh_red = sh_h;
#pragma unroll
        for (int g = 0; g < 4; ++g)
#pragma unroll
            for (int bi = 0; bi < 4; ++bi)
                *(u64*)&sh_red[ks * 1088 + (bg * 4 + bi) * 34 + g * 8 + jg * 2] =
                    acc2[g][bi];
        __syncthreads();

        float z[4];
#pragma unroll
        for (int g = 0; g < 4; ++g) {
            float s = 0.0f;
#pragma unroll
            for (int q = 0; q < 8; ++q)
                s += sh_red[q * 1088 + rb * 34 + g * 8 + rj];
            z[g] = s;
        }
        const float* xp = g_xp + ((size_t)t * 32 + rb) * 4096 + jb8 + rj;
        float zi = z[0] + xp[0];
        float zf = z[1] + xp[1024];
        float zg = z[2] + xp[2048];
        float zc = z[3] + xp[3072];

        float ig = 1.0f / (1.0f + __expf(-zi));
        float fg = 1.0f / (1.0f + __expf(-zf));
        float gg = 1.0f / (1.0f + __expf(-zg));
        float ct = tanhf(zc);
        c = fg * c + ig * ct;
        float h = gg * tanhf(c);

        g_states[((size_t)t * 32 + rb) * HH + jb8 + rj] = h;
        g_hT[(size_t)(jb8 + rj) * 32 + rb] = h;

        grid_sync();
    }
}

// ---------------------------------------------------------------------------
// Launch
// ---------------------------------------------------------------------------
extern "C" void kernel_launch(void* const* d_in, const int* in_sizes, int n_in,
                              void* d_out, int out_size)
{
    const float* x  = (const float*)d_in[0];
    const float* Wi = (const float*)d_in[1];
    const float* Ui = (const float*)d_in[2];
    const float* Wf = (const float*)d_in[3];
    const float* Uf = (const float*)d_in[4];
    const float* Wg = (const float*)d_in[5];
    const float* Ug = (const float*)d_in[6];
    const float* Wc = (const float*)d_in[7];
    const float* Uc = (const float*)d_in[8];
    const float* Wo = (const float*)d_in[9];
    const float* bi = (const float*)d_in[10];
    const float* bf_ = (const float*)d_in[11];
    const float* bg = (const float*)d_in[12];
    const float* bc = (const float*)d_in[13];
    const float* bo = (const float*)d_in[14];
    float* out = (float*)d_out;

    static bool attr_set = false;
    if (!attr_set) {
        cudaFuncSetAttribute(k_recurrent,
                             cudaFuncAttributeMaxDynamicSharedMemorySize, SMEM2_BYTES);
        cudaFuncSetAttribute(k_gemm_tc,
                             cudaFuncAttributeMaxDynamicSharedMemorySize, GSMEM_BYTES);
        attr_set = true;
    }

    static void *pA0 = nullptr, *pA1, *pB0, *pB1, *pWo0, *pWo1, *pbias4;
    if (!pA0) {
        cudaGetSymbolAddress(&pA0, g_A0);
        cudaGetSymbolAddress(&pA1, g_A1);
        cudaGetSymbolAddress(&pB0, g_B0);
        cudaGetSymbolAddress(&pB1, g_B1);
        cudaGetSymbolAddress(&pWo0, g_Wo0);
        cudaGetSymbolAddress(&pWo1, g_Wo1);
        cudaGetSymbolAddress(&pbias4, g_bias4);
    }

    // ---- conversions ----
    k_conv_x<<<16384, 256>>>(x);
    dim3 tb(32, 8);
    k_transpose_split<<<dim3(32, 32), tb>>>(Wi, (__nv_bfloat16*)pB0, (__nv_bfloat16*)pB1, 0);
    k_transpose_split<<<dim3(32, 32), tb>>>(Wf, (__nv_bfloat16*)pB0, (__nv_bfloat16*)pB1, 1024);
    k_transpose_split<<<dim3(32, 32), tb>>>(Wg, (__nv_bfloat16*)pB0, (__nv_bfloat16*)pB1, 2048);
    k_transpose_split<<<dim3(32, 32), tb>>>(Wc, (__nv_bfloat16*)pB0, (__nv_bfloat16*)pB1, 3072);
    k_transpose_split<<<dim3(32, 32), tb>>>(Wo, (__nv_bfloat16*)pWo0, (__nv_bfloat16*)pWo1, 0);
    k_bias_concat<<<16, 256>>>(bi, bf_, bg, bc);

    // ---- k1: input projection (tensor cores) ----
    k_gemm_tc<<<dim3(32, 128), 256, GSMEM_BYTES>>>(
        (const __nv_bfloat16*)pA0, (const __nv_bfloat16*)pA1,
        (const __nv_bfloat16*)pB0, (const __nv_bfloat16*)pB1,
        (const float*)pbias4, nullptr, 0);

    // ---- k2: recurrence ----
    k_recurrent<<<NBLK2, 256, SMEM2_BYTES>>>(Ui, Uf, Ug, Uc);

    // ---- k3: output projection (tensor cores) ----
    k_conv_states<<<16384, 256>>>();
    k_gemm_tc<<<dim3(8, 128), 256, GSMEM_BYTES>>>(
        (const __nv_bfloat16*)pA0, (const __nv_bfloat16*)pA1,
        (const __nv_bfloat16*)pWo0, (const __nv_bfloat16*)pWo1,
        bo, out, 1);
}

// round 9
// speedup vs baseline: 1.5858x; 1.2619x over previous
#include <cuda_runtime.h>
#include <cuda_bf16.h>
#include <math.h>
#include <stdint.h>

// ---------------------------------------------------------------------------
// LSTM layer: B=32, T=512, D=1024, H=1024
// k1/k3: bf16x3 split GEMM via mma.sync.  k2: persistent recurrent kernel,
// now ALSO tensor-core (bf16x3, M=32 x N=32 x K=1024 per block per step).
// ---------------------------------------------------------------------------

#define BB 32
#define TT 512
#define DD 1024
#define HH 1024

typedef unsigned long long u64;

// ---------------- PTX helpers (base-target only) ----------------
__device__ __forceinline__ void cp_async16(void* smem_dst, const void* gsrc) {
    unsigned s = (unsigned)__cvta_generic_to_shared(smem_dst);
    asm volatile("cp.async.cg.shared.global [%0], [%1], 16;" :: "r"(s), "l"(gsrc));
}
#define CP_COMMIT() asm volatile("cp.async.commit_group;")
#define CP_WAIT(n)  asm volatile("cp.async.wait_group %0;" :: "n"(n))

__device__ __forceinline__ uint32_t smem_u32(const void* p) {
    return (uint32_t)__cvta_generic_to_shared(p);
}
__device__ __forceinline__ void ldm_x4(uint32_t* r, uint32_t addr) {
    asm volatile("ldmatrix.sync.aligned.m8n8.x4.shared.b16 {%0,%1,%2,%3}, [%4];"
        : "=r"(r[0]), "=r"(r[1]), "=r"(r[2]), "=r"(r[3]) : "r"(addr));
}
__device__ __forceinline__ void ldm_x2(uint32_t* r, uint32_t addr) {
    asm volatile("ldmatrix.sync.aligned.m8n8.x2.shared.b16 {%0,%1}, [%2];"
        : "=r"(r[0]), "=r"(r[1]) : "r"(addr));
}
__device__ __forceinline__ void mma_bf16(float* d, const uint32_t* a,
                                         uint32_t b0, uint32_t b1) {
    asm volatile(
        "mma.sync.aligned.m16n8k16.row.col.f32.bf16.bf16.f32 "
        "{%0,%1,%2,%3}, {%4,%5,%6,%7}, {%8,%9}, {%0,%1,%2,%3};"
        : "+f"(d[0]), "+f"(d[1]), "+f"(d[2]), "+f"(d[3])
        : "r"(a[0]), "r"(a[1]), "r"(a[2]), "r"(a[3]), "r"(b0), "r"(b1));
}

// ---------------- scratch globals ----------------
__device__ float g_xp[(size_t)TT * BB * 4 * HH];      // 256 MB
__device__ float g_states[(size_t)TT * BB * HH];      // 64 MB
__device__ __nv_bfloat16 g_h0[(size_t)BB * HH];       // h hi  [b][k]
__device__ __nv_bfloat16 g_h1[(size_t)BB * HH];       // h lo  [b][k]
__device__ unsigned g_bar_count = 0;
__device__ unsigned g_bar_gen = 0;

__device__ __nv_bfloat16 g_A0[(size_t)16384 * 1024];  // A hi (x, later states)
__device__ __nv_bfloat16 g_A1[(size_t)16384 * 1024];  // A lo
__device__ __nv_bfloat16 g_B0[(size_t)4096 * 1024];   // W^T hi  [n][k]
__device__ __nv_bfloat16 g_B1[(size_t)4096 * 1024];   // W^T lo
__device__ __nv_bfloat16 g_Wo0[(size_t)1024 * 1024];  // Wo^T hi
__device__ __nv_bfloat16 g_Wo1[(size_t)1024 * 1024];  // Wo^T lo
__device__ __nv_bfloat16 g_Ut0[(size_t)128 * 8 * 32 * 128];  // U tiled hi: [blk][ch][n][128k]
__device__ __nv_bfloat16 g_Ut1[(size_t)128 * 8 * 32 * 128];  // U tiled lo
__device__ float g_bias4[4096];

// ===========================================================================
// Conversion kernels
// ===========================================================================
__global__ void k_conv_x(const float* __restrict__ x)   // grid 16384, block 256
{
    const int m = blockIdx.x;                 // m = t*32 + b
    const float* row = x + ((size_t)(m & 31) * TT + (m >> 5)) * DD;
    const int c = threadIdx.x * 4;
    float4 v = *(const float4*)&row[c];
    __nv_bfloat16 h0 = __float2bfloat16(v.x), h1 = __float2bfloat16(v.y);
    __nv_bfloat16 h2 = __float2bfloat16(v.z), h3 = __float2bfloat16(v.w);
    __nv_bfloat16 l0 = __float2bfloat16(v.x - __bfloat162float(h0));
    __nv_bfloat16 l1 = __float2bfloat16(v.y - __bfloat162float(h1));
    __nv_bfloat16 l2 = __float2bfloat16(v.z - __bfloat162float(h2));
    __nv_bfloat16 l3 = __float2bfloat16(v.w - __bfloat162float(h3));
    size_t o = (size_t)m * 1024 + c;
    *(ushort4*)&g_A0[o] = make_ushort4(*(unsigned short*)&h0, *(unsigned short*)&h1,
                                       *(unsigned short*)&h2, *(unsigned short*)&h3);
    *(ushort4*)&g_A1[o] = make_ushort4(*(unsigned short*)&l0, *(unsigned short*)&l1,
                                       *(unsigned short*)&l2, *(unsigned short*)&l3);
}

__global__ void k_conv_states()                         // grid 16384, block 256
{
    const int m = blockIdx.x;
    const float* row = g_states + (size_t)m * 1024;
    const int c = threadIdx.x * 4;
    float4 v = *(const float4*)&row[c];
    __nv_bfloat16 h0 = __float2bfloat16(v.x), h1 = __float2bfloat16(v.y);
    __nv_bfloat16 h2 = __float2bfloat16(v.z), h3 = __float2bfloat16(v.w);
    __nv_bfloat16 l0 = __float2bfloat16(v.x - __bfloat162float(h0));
    __nv_bfloat16 l1 = __float2bfloat16(v.y - __bfloat162float(h1));
    __nv_bfloat16 l2 = __float2bfloat16(v.z - __bfloat162float(h2));
    __nv_bfloat16 l3 = __float2bfloat16(v.w - __bfloat162float(h3));
    size_t o = (size_t)m * 1024 + c;
    *(ushort4*)&g_A0[o] = make_ushort4(*(unsigned short*)&h0, *(unsigned short*)&h1,
                                       *(unsigned short*)&h2, *(unsigned short*)&h3);
    *(ushort4*)&g_A1[o] = make_ushort4(*(unsigned short*)&l0, *(unsigned short*)&l1,
                                       *(unsigned short*)&l2, *(unsigned short*)&l3);
}

// transpose + split: W[k][n] -> d[orow_base + n][k] (hi/lo), flat layout
__global__ void k_transpose_split(const float* __restrict__ W,
                                  __nv_bfloat16* __restrict__ d0,
                                  __nv_bfloat16* __restrict__ d1,
                                  int orow_base)       // grid (32, 32), block (32,8)
{
    __shared__ float tile[32][33];
    const int kt = blockIdx.x * 32, nt = blockIdx.y * 32;
    const int tx = threadIdx.x, ty = threadIdx.y;
#pragma unroll
    for (int i = 0; i < 4; ++i)
        tile[ty + 8 * i][tx] = W[(size_t)(kt + ty + 8 * i) * 1024 + nt + tx];
    __syncthreads();
#pragma unroll
    for (int i = 0; i < 4; ++i) {
        float v = tile[tx][ty + 8 * i];
        __nv_bfloat16 hi = __float2bfloat16(v);
        __nv_bfloat16 lo = __float2bfloat16(v - __bfloat162float(hi));
        size_t o = (size_t)(orow_base + nt + ty + 8 * i) * 1024 + kt + tx;
        d0[o] = hi; d1[o] = lo;
    }
}

// transpose + split U into per-block tiled layout:
// g_Ut[((j>>3)*8 + (k>>7))*4096 + (g*8 + (j&7))*128 + (k&127)]
__global__ void k_transpose_split_U(const float* __restrict__ U, int g)
{                                                     // grid (32, 32), block (32,8)
    __shared__ float tile[32][33];
    const int kt = blockIdx.x * 32, nt = blockIdx.y * 32;
    const int tx = threadIdx.x, ty = threadIdx.y;
#pragma unroll
    for (int i = 0; i < 4; ++i)
        tile[ty + 8 * i][tx] = U[(size_t)(kt + ty + 8 * i) * 1024 + nt + tx];
    __syncthreads();
#pragma unroll
    for (int i = 0; i < 4; ++i) {
        float v = tile[tx][ty + 8 * i];
        __nv_bfloat16 hi = __float2bfloat16(v);
        __nv_bfloat16 lo = __float2bfloat16(v - __bfloat162float(hi));
        const int j = nt + ty + 8 * i;
        const int k = kt + tx;
        size_t o = ((size_t)(j >> 3) * 8 + (k >> 7)) * 4096
                 + (size_t)(g * 8 + (j & 7)) * 128 + (k & 127);
        g_Ut0[o] = hi; g_Ut1[o] = lo;
    }
}

__global__ void k_bias_concat(const float* bi, const float* bf_,
                              const float* bg, const float* bc)  // grid 16, block 256
{
    int idx = blockIdx.x * 256 + threadIdx.x;
    int g = idx >> 10, j = idx & 1023;
    const float* b = (g == 0) ? bi : (g == 1) ? bf_ : (g == 2) ? bg : bc;
    g_bias4[idx] = b[j];
}

// ===========================================================================
// bf16x3 GEMM via mma.sync (validated R6 version, unchanged)
// ===========================================================================
#define TROW 80
#define TILE_BYTES (128 * TROW)
#define STAGE_BYTES (4 * TILE_BYTES)
#define GSMEM_BYTES (2 * STAGE_BYTES)

__global__ void __launch_bounds__(256) k_gemm_tc(
    const __nv_bfloat16* __restrict__ A0, const __nv_bfloat16* __restrict__ A1,
    const __nv_bfloat16* __restrict__ B0, const __nv_bfloat16* __restrict__ B1,
    const float* __restrict__ bias, float* __restrict__ outp, int mode)
{
    extern __shared__ char smem[];
    __shared__ float sh_bias[128];

    const int tid = threadIdx.x;
    const int wid = tid >> 5;
    const int lane = tid & 31;
    const int nblk = blockIdx.x * 128;
    const int mblk = blockIdx.y * 128;

    const int wm = (wid >> 1) * 32;
    const int wn = (wid & 1) * 64;

    if (tid < 128) sh_bias[tid] = bias[nblk + tid];

    const char* srcs[4] = {
        (const char*)(A0 + (size_t)mblk * 1024),
        (const char*)(A1 + (size_t)mblk * 1024),
        (const char*)(B0 + (size_t)nblk * 1024),
        (const char*)(B1 + (size_t)nblk * 1024) };

#define LOAD_CHUNK(kc, s) do {                                                  \
        char* stg = smem + (s) * STAGE_BYTES;                                    \
        _Pragma("unroll")                                                        \
        for (int i = 0; i < 8; ++i) {                                            \
            const int ch = tid + i * 256;                                        \
            const int tix = ch >> 9;                                             \
            const int q = ch & 511;                                              \
            const int r = q >> 2;                                                \
            const int cc = q & 3;                                                \
            cp_async16(stg + tix * TILE_BYTES + r * TROW + cc * 16,              \
                       srcs[tix] + (size_t)r * 2048 + (kc) * 64 + cc * 16);      \
        }                                                                        \
        CP_COMMIT();                                                             \
    } while (0)

    float acc[2][8][4];
#pragma unroll
    for (int mt = 0; mt < 2; ++mt)
#pragma unroll
        for (int nb = 0; nb < 8; ++nb)
#pragma unroll
            for (int r = 0; r < 4; ++r) acc[mt][nb][r] = 0.0f;

    LOAD_CHUNK(0, 0);

#pragma unroll 1
    for (int c = 0; c < 32; ++c) {
        const int cur = c & 1;
        if (c + 1 < 32) {
            LOAD_CHUNK(c + 1, cur ^ 1);
            CP_WAIT(1);
        } else {
            CP_WAIT(0);
        }
        __syncthreads();

        const uint32_t stg = smem_u32(smem) + cur * STAGE_BYTES;
        const uint32_t sA0 = stg;
        const uint32_t sA1 = stg + TILE_BYTES;
        const uint32_t sB0 = stg + 2 * TILE_BYTES;
        const uint32_t sB1 = stg + 3 * TILE_BYTES;

#pragma unroll
        for (int kt = 0; kt < 2; ++kt) {
            const uint32_t koff = kt * 32 + (lane >> 4) * 16;
            uint32_t a0f[2][4], a1f[2][4], b0f[4][4], b1f[4][4];
#pragma unroll
            for (int mt = 0; mt < 2; ++mt) {
                const uint32_t rb = (wm + mt * 16 + (lane & 15)) * TROW + koff;
                ldm_x4(a0f[mt], sA0 + rb);
                ldm_x4(a1f[mt], sA1 + rb);
            }
#pragma unroll
            for (int nt = 0; nt < 4; ++nt) {
                const uint32_t rb = (wn + nt * 16 + (lane & 15)) * TROW + koff;
                ldm_x4(b0f[nt], sB0 + rb);
                ldm_x4(b1f[nt], sB1 + rb);
            }
#pragma unroll
            for (int mt = 0; mt < 2; ++mt)
#pragma unroll
                for (int nb = 0; nb < 8; ++nb) {
                    const int nt = nb >> 1, h = nb & 1;
                    mma_bf16(acc[mt][nb], a0f[mt], b0f[nt][h], b0f[nt][h + 2]);
                    mma_bf16(acc[mt][nb], a0f[mt], b1f[nt][h], b1f[nt][h + 2]);
                    mma_bf16(acc[mt][nb], a1f[mt], b0f[nt][h], b0f[nt][h + 2]);
                }
        }
        __syncthreads();
    }

    const int mrow0 = mblk + wm + (lane >> 2);
    const int ncol0 = wn + 2 * (lane & 3);
#pragma unroll
    for (int mt = 0; mt < 2; ++mt)
#pragma unroll
        for (int nb = 0; nb < 8; ++nb) {
            const int n = ncol0 + nb * 8;
            const float bx = sh_bias[n], by = sh_bias[n + 1];
#pragma unroll
            for (int half = 0; half < 2; ++half) {
                const int m = mrow0 + mt * 16 + half * 8;
                float ox = acc[mt][nb][half * 2 + 0] + bx;
                float oy = acc[mt][nb][half * 2 + 1] + by;
                if (mode == 1) { ox = fmaxf(ox, 0.f); oy = fmaxf(oy, 0.f); }
                float* dst;
                if (mode == 0)
                    dst = g_xp + (size_t)m * 4096 + nblk + n;
                else
                    dst = outp + ((size_t)(m & 31) * TT + (m >> 5)) * 1024 + nblk + n;
                *(float2*)dst = make_float2(ox, oy);
            }
        }
}

// ===========================================================================
// Kernel 2: persistent recurrent kernel — TENSOR CORE version.
// 128 blocks x 256 threads (8 warps), 1 block/SM (178KB smem).
// Block: GEMM M=32(b) x N=32(4g x 8j) x K=1024 in bf16x3 via mma.sync.
// Warp w: m-tile (w>>2)*16, gate w&3 (8 n). 192 MMA/warp/step, no k-split.
// U resident in smem (tiled, 272B rows). h staged in 8 chunks, dbl-buffered.
// ===========================================================================
#define NBLK2 128
#define TROW2 272
#define UTILE (8 * 32 * TROW2)          /* 69632 per matrix */
#define U_OFF 0
#define HTILE (32 * TROW2)              /* 8704 per matrix */
#define HSTAGE (2 * HTILE)              /* 17408 per stage (hi+lo) */
#define STG_OFF (2 * UTILE)             /* 139264 */
#define Z_OFF (STG_OFF + 2 * HSTAGE)    /* 174080 */
#define SMEM2_BYTES (Z_OFF + 32 * 34 * 4)  /* 178432 */

__device__ __forceinline__ void grid_sync()
{
    __syncthreads();
    if (threadIdx.x == 0) {
        __threadfence();
        unsigned gen = *(volatile unsigned*)&g_bar_gen;
        unsigned t = atomicAdd(&g_bar_count, 1);
        if (t == NBLK2 - 1) {
            g_bar_count = 0;
            __threadfence();
            atomicExch(&g_bar_gen, gen + 1);
        } else {
            while (*(volatile unsigned*)&g_bar_gen == gen) { }
            __threadfence();
        }
    }
    __syncthreads();
}

__global__ void __launch_bounds__(256, 1) k_recurrent_tc(
    const __nv_bfloat16* __restrict__ Ut0, const __nv_bfloat16* __restrict__ Ut1)
{
    extern __shared__ char smem[];
    float* shz = (float*)(smem + Z_OFF);

    const int tid = threadIdx.x;
    const int wid = tid >> 5;
    const int lane = tid & 31;
    const int jb8 = blockIdx.x * 8;

    const int wm = (wid >> 2) * 16;        // m-tile base (0 or 16)
    const int wg = wid & 3;                // gate for this warp
    const uint32_t sb0 = smem_u32(smem);

    // ---- load U tiles into smem once (128KB via cp.async) ----
    {
        const char* u0g = (const char*)Ut0 + (size_t)blockIdx.x * 65536;
        const char* u1g = (const char*)Ut1 + (size_t)blockIdx.x * 65536;
#pragma unroll 4
        for (int i = tid; i < 8192; i += 256) {   // 16B units
            const int mat = i >> 12;
            const int rem = i & 4095;
            const int rn = rem >> 4;              // (ch*32+n)
            const int cc = rem & 15;
            const char* g = (mat ? u1g : u0g) + rn * 256 + cc * 16;
            cp_async16(smem + U_OFF + mat * UTILE + rn * TROW2 + cc * 16, g);
        }
        CP_COMMIT();
        CP_WAIT(0);
    }
    __syncthreads();

    // output identity: (rb, rj) owns (b=rb, j=jb8+rj)
    const int rb = tid >> 3;
    const int rj = tid & 7;
    float cstate = 0.0f;

    // ldmatrix address components (precomputed)
    const int l15 = lane & 15;
    const uint32_t a_row = (uint32_t)(l15 * TROW2 + (lane >> 4) * 16);
    const uint32_t b_row = (uint32_t)((wg * 8 + (l15 & 7)) * TROW2 + ((l15 >> 3) & 1) * 16);

#define LOADH(kc, s) do {                                                       \
        char* stg = smem + STG_OFF + (s) * HSTAGE;                               \
        _Pragma("unroll")                                                        \
        for (int i = 0; i < 4; ++i) {                                            \
            const int idx = tid + i * 256;                                       \
            const int mat = idx >> 9;                                            \
            const int rem = idx & 511;                                           \
            const int r = rem >> 4;                                              \
            const int cc = rem & 15;                                             \
            const char* src = (mat ? (const char*)g_h1 : (const char*)g_h0)      \
                              + (size_t)r * 2048 + (kc) * 256 + cc * 16;         \
            cp_async16(stg + mat * HTILE + r * TROW2 + cc * 16, src);            \
        }                                                                        \
        CP_COMMIT();                                                             \
    } while (0)

    for (int t = 0; t < TT; ++t) {
        float z[4];

        if (t == 0) {
            z[0] = 0.f; z[1] = 0.f; z[2] = 0.f; z[3] = 0.f;
        } else {
            float acc[4] = {0.f, 0.f, 0.f, 0.f};

            LOADH(0, 0);
#pragma unroll 1
            for (int c = 0; c < 8; ++c) {
                if (c < 7) { LOADH(c + 1, (c + 1) & 1); CP_WAIT(1); }
                else       { CP_WAIT(0); }
                __syncthreads();

                const uint32_t hA0 = sb0 + STG_OFF + (c & 1) * HSTAGE;
                const uint32_t hA1 = hA0 + HTILE;
                const uint32_t uB0 = sb0 + U_OFF + c * HTILE;
                const uint32_t uB1 = uB0 + UTILE;

#pragma unroll
                for (int kk = 0; kk < 8; ++kk) {
                    const uint32_t ka = (uint32_t)(wm * TROW2 + kk * 32) + a_row;
                    const uint32_t kb = (uint32_t)(kk * 32) + b_row;
                    uint32_t a0f[4], a1f[4], b0f[2], b1f[2];
                    ldm_x4(a0f, hA0 + ka);
                    ldm_x4(a1f, hA1 + ka);
                    ldm_x2(b0f, uB0 + kb);
                    ldm_x2(b1f, uB1 + kb);
                    mma_bf16(acc, a0f, b0f[0], b0f[1]);
                    mma_bf16(acc, a0f, b1f[0], b1f[1]);
                    mma_bf16(acc, a1f, b0f[0], b0f[1]);
                }
                __syncthreads();
            }

            // ---- z exchange: warp w holds (16b x 8n) tile for gate wg ----
            {
                const int brow0 = wm + (lane >> 2);
                const int col0 = wg * 8 + 2 * (lane & 3);
                *(float2*)&shz[brow0 * 34 + col0] = make_float2(acc[0], acc[1]);
                *(float2*)&shz[(brow0 + 8) * 34 + col0] = make_float2(acc[2], acc[3]);
            }
            __syncthreads();

#pragma unroll
            for (int g = 0; g < 4; ++g)
                z[g] = shz[rb * 34 + g * 8 + rj];
            __syncthreads();
        }

        // ---- gates + state update ----
        const float* xp = g_xp + ((size_t)t * 32 + rb) * 4096 + jb8 + rj;
        float zi = z[0] + xp[0];
        float zf = z[1] + xp[1024];
        float zg = z[2] + xp[2048];
        float zc = z[3] + xp[3072];

        float ig = 1.0f / (1.0f + __expf(-zi));
        float fg = 1.0f / (1.0f + __expf(-zf));
        float gg = 1.0f / (1.0f + __expf(-zg));
        float ct = tanhf(zc);
        cstate = fg * cstate + ig * ct;
        float h = gg * tanhf(cstate);

        g_states[((size_t)t * 32 + rb) * HH + jb8 + rj] = h;
        __nv_bfloat16 hh = __float2bfloat16(h);
        __nv_bfloat16 hl = __float2bfloat16(h - __bfloat162float(hh));
        g_h0[(size_t)rb * HH + jb8 + rj] = hh;
        g_h1[(size_t)rb * HH + jb8 + rj] = hl;

        grid_sync();
    }
}

// ---------------------------------------------------------------------------
// Launch
// ---------------------------------------------------------------------------
extern "C" void kernel_launch(void* const* d_in, const int* in_sizes, int n_in,
                              void* d_out, int out_size)
{
    const float* x  = (const float*)d_in[0];
    const float* Wi = (const float*)d_in[1];
    const float* Ui = (const float*)d_in[2];
    const float* Wf = (const float*)d_in[3];
    const float* Uf = (const float*)d_in[4];
    const float* Wg = (const float*)d_in[5];
    const float* Ug = (const float*)d_in[6];
    const float* Wc = (const float*)d_in[7];
    const float* Uc = (const float*)d_in[8];
    const float* Wo = (const float*)d_in[9];
    const float* bi = (const float*)d_in[10];
    const float* bf_ = (const float*)d_in[11];
    const float* bg = (const float*)d_in[12];
    const float* bc = (const float*)d_in[13];
    const float* bo = (const float*)d_in[14];
    float* out = (float*)d_out;

    static bool attr_set = false;
    if (!attr_set) {
        cudaFuncSetAttribute(k_recurrent_tc,
                             cudaFuncAttributeMaxDynamicSharedMemorySize, SMEM2_BYTES);
        cudaFuncSetAttribute(k_gemm_tc,
                             cudaFuncAttributeMaxDynamicSharedMemorySize, GSMEM_BYTES);
        attr_set = true;
    }

    static void *pA0 = nullptr, *pA1, *pB0, *pB1, *pWo0, *pWo1, *pbias4, *pUt0, *pUt1;
    if (!pA0) {
        cudaGetSymbolAddress(&pA0, g_A0);
        cudaGetSymbolAddress(&pA1, g_A1);
        cudaGetSymbolAddress(&pB0, g_B0);
        cudaGetSymbolAddress(&pB1, g_B1);
        cudaGetSymbolAddress(&pWo0, g_Wo0);
        cudaGetSymbolAddress(&pWo1, g_Wo1);
        cudaGetSymbolAddress(&pbias4, g_bias4);
        cudaGetSymbolAddress(&pUt0, g_Ut0);
        cudaGetSymbolAddress(&pUt1, g_Ut1);
    }

    // ---- conversions ----
    k_conv_x<<<16384, 256>>>(x);
    dim3 tb(32, 8);
    k_transpose_split<<<dim3(32, 32), tb>>>(Wi, (__nv_bfloat16*)pB0, (__nv_bfloat16*)pB1, 0);
    k_transpose_split<<<dim3(32, 32), tb>>>(Wf, (__nv_bfloat16*)pB0, (__nv_bfloat16*)pB1, 1024);
    k_transpose_split<<<dim3(32, 32), tb>>>(Wg, (__nv_bfloat16*)pB0, (__nv_bfloat16*)pB1, 2048);
    k_transpose_split<<<dim3(32, 32), tb>>>(Wc, (__nv_bfloat16*)pB0, (__nv_bfloat16*)pB1, 3072);
    k_transpose_split<<<dim3(32, 32), tb>>>(Wo, (__nv_bfloat16*)pWo0, (__nv_bfloat16*)pWo1, 0);
    k_transpose_split_U<<<dim3(32, 32), tb>>>(Ui, 0);
    k_transpose_split_U<<<dim3(32, 32), tb>>>(Uf, 1);
    k_transpose_split_U<<<dim3(32, 32), tb>>>(Ug, 2);
    k_transpose_split_U<<<dim3(32, 32), tb>>>(Uc, 3);
    k_bias_concat<<<16, 256>>>(bi, bf_, bg, bc);

    // ---- k1: input projection (tensor cores) ----
    k_gemm_tc<<<dim3(32, 128), 256, GSMEM_BYTES>>>(
        (const __nv_bfloat16*)pA0, (const __nv_bfloat16*)pA1,
        (const __nv_bfloat16*)pB0, (const __nv_bfloat16*)pB1,
        (const float*)pbias4, nullptr, 0);

    // ---- k2: recurrence (tensor cores) ----
    k_recurrent_tc<<<NBLK2, 256, SMEM2_BYTES>>>(
        (const __nv_bfloat16*)pUt0, (const __nv_bfloat16*)pUt1);

    // ---- k3: output projection (tensor cores) ----
    k_conv_states<<<16384, 256>>>();
    k_gemm_tc<<<dim3(8, 128), 256, GSMEM_BYTES>>>(
        (const __nv_bfloat16*)pA0, (const __nv_bfloat16*)pA1,
        (const __nv_bfloat16*)pWo0, (const __nv_bfloat16*)pWo1,
        bo, out, 1);
}